// round 1
// baseline (speedup 1.0000x reference)
#include <cuda_runtime.h>

// Temporal_Attention: algebraically collapsed form.
// B=64, T=256, D=128, H=8, E=128. Output [B, D] fp32.
//
// summary[b,h,t] = x[b,t]·u[b,h] + c[b,h]
//   xs[b]   = sum_t Ws[t] * x[b,t]                      (B x D)
//   S       = sum_t Ws[t]
//   Khat[b,he] = xs[b]·Wk[:,he] + bk[he]*S              (B x H*E)
//   u[b,h]  = scale * Wq_h @ Khat[b,h]                  (B x H x D)
//   c[b,h]  = scale * bq_h·Khat[b,h] + bs
// beta = softmax_t(summary)
//   y[b,h]  = sum_t beta[b,h,t] * x[b,t]                (B x H x D)
// out[b]   = sum_h y[b,h] @ M_h + cbias
//   M_h     = Wv_h @ Wo_h  (D x D per head)
//   cbias   = bo + sum_he bv[he]*Wo[he,:]

#define BB 64
#define TT 256
#define DD 128
#define HH 8
#define HE 1024

static __device__ float g_xs[BB * DD];
static __device__ float g_S;
static __device__ float g_Khat[BB * HE];
static __device__ float g_u[BB * HH * DD];
static __device__ float g_c[BB * HH];
static __device__ float g_y[BB * HH * DD];
static __device__ float g_M[HH * DD * DD];
static __device__ float g_cbias[DD];
static __device__ float g_part[4 * BB * DD];

// ---------------------------------------------------------------------------
// K1: weight-only precompute.  blocks 0..1023 -> M[h][d1][:], block 1024 -> cbias
__global__ void k_weights(const float* __restrict__ Wv, const float* __restrict__ bv,
                          const float* __restrict__ Wo, const float* __restrict__ bo) {
    int blk = blockIdx.x;
    int tid = threadIdx.x;  // 128
    if (blk < HH * DD) {
        int h = blk >> 7, d1 = blk & 127;
        __shared__ float sv[DD];
        sv[tid] = Wv[d1 * HE + h * DD + tid];
        __syncthreads();
        float acc = 0.f;
        const float* wo = Wo + (h * DD) * DD + tid;
        #pragma unroll 8
        for (int e = 0; e < DD; e++) acc += sv[e] * wo[e * DD];
        g_M[blk * DD + tid] = acc;
    } else {
        float acc = bo[tid];
        #pragma unroll 8
        for (int k = 0; k < HE; k++) acc += bv[k] * Wo[k * DD + tid];
        g_cbias[tid] = acc;
    }
}

// ---------------------------------------------------------------------------
// K2: xs[b] = sum_t Ws[t]*x[b,t],  S = sum_t Ws[t].  grid 64, 128 thr.
__global__ void k_xs(const float* __restrict__ x, const float* __restrict__ Ws) {
    int b = blockIdx.x, d = threadIdx.x;
    float acc = 0.f;
    const float* xp = x + b * TT * DD + d;
    #pragma unroll 8
    for (int t = 0; t < TT; t++) acc += Ws[t] * xp[t * DD];
    g_xs[b * DD + d] = acc;
    if (b == 0 && d == 0) {
        float s = 0.f;
        for (int t = 0; t < TT; t++) s += Ws[t];
        g_S = s;
    }
}

// ---------------------------------------------------------------------------
// K3: Khat[b,k] = xs[b]·Wk[:,k] + bk[k]*S.  grid 64, 256 thr.
__global__ void k_khat(const float* __restrict__ Wk, const float* __restrict__ bk) {
    int b = blockIdx.x, tid = threadIdx.x;
    __shared__ float sx[DD];
    if (tid < DD) sx[tid] = g_xs[b * DD + tid];
    __syncthreads();
    float S = g_S;
    for (int k = tid; k < HE; k += 256) {
        float acc = bk[k] * S;
        #pragma unroll 8
        for (int d = 0; d < DD; d++) acc += sx[d] * Wk[d * HE + k];
        g_Khat[b * HE + k] = acc;
    }
}

// ---------------------------------------------------------------------------
// K4: u[b,h,d] = scale * sum_e Wq[d,h*E+e]*Khat[b,h,e]; c[b,h].  grid 512, 128 thr.
__global__ void k_u(const float* __restrict__ Wq, const float* __restrict__ bq,
                    const float* __restrict__ bs) {
    int bh = blockIdx.x;
    int b = bh >> 3, h = bh & 7;
    int tid = threadIdx.x;
    __shared__ float kh[DD];
    __shared__ float red[DD];
    float kv = g_Khat[b * HE + h * DD + tid];
    kh[tid] = kv;
    red[tid] = kv * bq[h * DD + tid];
    __syncthreads();
    for (int s = 64; s > 0; s >>= 1) {
        if (tid < s) red[tid] += red[tid + s];
        __syncthreads();
    }
    const float scale = 0.088388347648318447f;  // 1/sqrt(128)
    if (tid == 0) g_c[bh] = scale * red[0] + bs[0];
    float acc = 0.f;
    const float4* wq4 = (const float4*)(Wq + tid * HE + h * DD);
    const float4* kh4 = (const float4*)kh;
    #pragma unroll 8
    for (int e4 = 0; e4 < DD / 4; e4++) {
        float4 w = wq4[e4];
        float4 k4 = kh4[e4];
        acc += w.x * k4.x + w.y * k4.y + w.z * k4.z + w.w * k4.w;
    }
    g_u[bh * DD + tid] = acc * scale;
}

// ---------------------------------------------------------------------------
// K5: per batch: summary -> softmax over t -> y[b,h,:].  grid 64, 256 thr.
__global__ void k_attn(const float* __restrict__ x) {
    int b = blockIdx.x, tid = threadIdx.x;
    __shared__ float su[HH * DD];    // 4 KB
    __shared__ float sc[HH];
    __shared__ float sbeta[HH * TT]; // 8 KB
    __shared__ float sy[HH * DD];    // 4 KB

    for (int i = tid; i < HH * DD; i += 256) su[i] = g_u[b * HH * DD + i];
    if (tid < HH) sc[tid] = g_c[b * HH + tid];
    __syncthreads();

    // phase 1: summary for t = tid (all 8 heads at once; x read once)
    {
        float acc[HH];
        #pragma unroll
        for (int h = 0; h < HH; h++) acc[h] = 0.f;
        const float4* xp = (const float4*)(x + (b * TT + tid) * DD);
        #pragma unroll 4
        for (int d4 = 0; d4 < DD / 4; d4++) {
            float4 xv = xp[d4];
            #pragma unroll
            for (int h = 0; h < HH; h++) {
                float4 uv = ((const float4*)(su + h * DD))[d4];
                acc[h] += xv.x * uv.x + xv.y * uv.y + xv.z * uv.z + xv.w * uv.w;
            }
        }
        #pragma unroll
        for (int h = 0; h < HH; h++) sbeta[h * TT + tid] = acc[h] + sc[h];
    }
    __syncthreads();

    // phase 2: softmax over t, one warp per head
    {
        int h = tid >> 5, lane = tid & 31;
        float v[8];
        float m = -1e30f;
        #pragma unroll
        for (int i = 0; i < 8; i++) {
            v[i] = sbeta[h * TT + lane + 32 * i];
            m = fmaxf(m, v[i]);
        }
        #pragma unroll
        for (int o = 16; o > 0; o >>= 1) m = fmaxf(m, __shfl_xor_sync(0xffffffffu, m, o));
        float s = 0.f;
        #pragma unroll
        for (int i = 0; i < 8; i++) { v[i] = __expf(v[i] - m); s += v[i]; }
        #pragma unroll
        for (int o = 16; o > 0; o >>= 1) s += __shfl_xor_sync(0xffffffffu, s, o);
        float inv = 1.f / s;
        #pragma unroll
        for (int i = 0; i < 8; i++) sbeta[h * TT + lane + 32 * i] = v[i] * inv;
    }
    __syncthreads();

    // phase 3: y[b,h,d] = sum_t beta[h,t]*x[b,t,d]; 2 t-halves of 128 threads each
    {
        int d = tid & 127, half = tid >> 7;
        float acc[HH];
        #pragma unroll
        for (int h = 0; h < HH; h++) acc[h] = 0.f;
        const float* xp = x + b * TT * DD + half * 128 * DD + d;
        #pragma unroll 2
        for (int t = 0; t < 128; t++) {
            float xv = xp[t * DD];
            int tt = half * 128 + t;
            #pragma unroll
            for (int h = 0; h < HH; h++) acc[h] += sbeta[h * TT + tt] * xv;
        }
        if (half == 1) {
            #pragma unroll
            for (int h = 0; h < HH; h++) sy[h * DD + d] = acc[h];
        }
        __syncthreads();
        if (half == 0) {
            #pragma unroll
            for (int h = 0; h < HH; h++)
                g_y[b * HH * DD + h * DD + d] = acc[h] + sy[h * DD + d];
        }
    }
}

// ---------------------------------------------------------------------------
// K6: partial out[b,d2] over k-quarters of the 1024-long contraction.
// grid (64, 4), 128 thr.
__global__ void k_out_part() {
    int b = blockIdx.x, q = blockIdx.y, tid = threadIdx.x;
    __shared__ float syb[256];
    syb[tid]       = g_y[b * HE + q * 256 + tid];
    syb[tid + 128] = g_y[b * HE + q * 256 + tid + 128];
    __syncthreads();
    float acc = 0.f;
    const float* mp = g_M + (q * 256) * DD + tid;
    #pragma unroll 8
    for (int k = 0; k < 256; k++) acc += syb[k] * mp[k * DD];
    g_part[(q * BB + b) * DD + tid] = acc;
}

// K7: reduce partials + cbias.  grid 64, 128 thr.
__global__ void k_out(float* __restrict__ out) {
    int b = blockIdx.x, tid = threadIdx.x;
    float acc = g_cbias[tid];
    #pragma unroll
    for (int q = 0; q < 4; q++) acc += g_part[(q * BB + b) * DD + tid];
    out[b * DD + tid] = acc;
}

// ---------------------------------------------------------------------------
extern "C" void kernel_launch(void* const* d_in, const int* in_sizes, int n_in,
                              void* d_out, int out_size) {
    const float* x  = (const float*)d_in[0];
    const float* Wq = (const float*)d_in[1];
    const float* bq = (const float*)d_in[2];
    const float* Wk = (const float*)d_in[3];
    const float* bk = (const float*)d_in[4];
    const float* Wv = (const float*)d_in[5];
    const float* bv = (const float*)d_in[6];
    const float* Ws = (const float*)d_in[7];
    const float* bs = (const float*)d_in[8];
    const float* Wo = (const float*)d_in[9];
    const float* bo = (const float*)d_in[10];
    float* out = (float*)d_out;

    k_weights<<<HH * DD + 1, 128>>>(Wv, bv, Wo, bo);
    k_xs<<<BB, 128>>>(x, Ws);
    k_khat<<<BB, 256>>>(Wk, bk);
    k_u<<<BB * HH, 128>>>(Wq, bq, bs);
    k_attn<<<BB, 256>>>(x);
    k_out_part<<<dim3(BB, 4), 128>>>();
    k_out<<<BB, 128>>>(out);
}

// round 2
// speedup vs baseline: 1.4120x; 1.4120x over previous
#include <cuda_runtime.h>

// Temporal_Attention, algebraically collapsed, 2 kernels.
// B=64, T=256, D=128, H=8, E=128.  out[B,D] fp32.
//
//  xs[b]      = sum_t Ws[t] x[b,t]            ; S = sum Ws
//  Khat[b,he] = xs[b].Wk[:,he] + bk[he] S
//  u[b,h,d]   = scale * sum_e Wq[d,he] Khat[b,he]
//  c[b,h]     = scale * sum_e bq[he] Khat[b,he] + bs
//  beta       = softmax_t( x[b,t].u[b,h] + c[b,h] )
//  y[b,h,d]   = sum_t beta x[b,t,d]
//  out[b,d2]  = sum_{h,d} y[b,h,d] M[(h,d),d2] + cbias[d2]
//  M_h = Wv_h @ Wo_h ;  cbias = bo + sum_he bv[he] Wo[he,:]

#define BB 64
#define TT 256
#define DD 128
#define HH 8
#define HE 1024

static __device__ float g_u[BB * HE];     // [b][h*128+d]
static __device__ float g_c[BB * HH];
static __device__ float g_M[HE * DD];     // [(h*128+d)][d2]
static __device__ float g_cbias[DD];

// ---------------------------------------------------------------------------
// Kernel 1: grid 97 x 256 threads.
//   blocks 0..31  : role A, 2 batches each: xs -> Khat -> c, u
//   blocks 32..95 : role B, M_h tiles (16 rows x 128 cols each)
//   block 96      : role C, cbias
__global__ __launch_bounds__(256) void k_pre(
    const float* __restrict__ x,  const float* __restrict__ Ws,
    const float* __restrict__ Wk, const float* __restrict__ bk,
    const float* __restrict__ Wq, const float* __restrict__ bq,
    const float* __restrict__ bs,
    const float* __restrict__ Wv, const float* __restrict__ bv,
    const float* __restrict__ Wo, const float* __restrict__ bo)
{
    __shared__ float s[9216];   // 36 KB, shared by all roles
    const int blk = blockIdx.x, tid = threadIdx.x;
    const int lane = tid & 31;
    const float scale = 0.088388347648318447f;  // 1/sqrt(128)

    if (blk < 32) {
        // ---------------- role A: batches b0, b0+1 ----------------
        float* sWs = s;            // 256
        float* red = s + 256;     // 256
        float* sxp = s + 512;     // 1024 (4 t-quarters x (bb,d))
        float* sx  = s + 1536;    // 256  (2 x 128)
        float* skh = s + 1792;    // 2048 (2 x 1024)
        float* tile= s + 3840;    // 128*33 = 4224 (padded Wq tile)
        const int b0 = blk * 2;
        const int bb = tid >> 7;        // which batch of the pair
        const int d  = tid & 127;

        // Ws into smem + total S
        {
            float w = Ws[tid];
            sWs[tid] = w;
            red[tid] = w;
        }
        __syncthreads();
        for (int st = 128; st > 0; st >>= 1) {
            if (tid < st) red[tid] += red[tid + st];
            __syncthreads();
        }
        const float S = red[0];

        // xs: vectorized float4, 4 t-quarters per batch
        {
            int q = (tid >> 5) & 3;
            const float4* x4 = (const float4*)x;
            float4 a = make_float4(0.f, 0.f, 0.f, 0.f);
            int base = ((b0 + bb) * TT) * 32 + lane;
            #pragma unroll 8
            for (int t = q * 64; t < q * 64 + 64; t++) {
                float wt = sWs[t];
                float4 xv = x4[base + t * 32];
                a.x += wt * xv.x; a.y += wt * xv.y;
                a.z += wt * xv.z; a.w += wt * xv.w;
            }
            ((float4*)sxp)[q * 64 + bb * 32 + lane] = a;
        }
        __syncthreads();
        sx[tid] = sxp[tid] + sxp[256 + tid] + sxp[512 + tid] + sxp[768 + tid];
        __syncthreads();

        // Khat: thread (bb,d) owns he in {4d..4d+3} and {512+4d..+3} (float4)
        {
            const float*  sxb = sx + bb * 128;
            const float4* Wk4 = (const float4*)Wk;
            const float4* bk4 = (const float4*)bk;
            float4 a0 = bk4[d], a1 = bk4[128 + d];
            a0.x *= S; a0.y *= S; a0.z *= S; a0.w *= S;
            a1.x *= S; a1.y *= S; a1.z *= S; a1.w *= S;
            #pragma unroll 4
            for (int d2 = 0; d2 < 128; d2++) {
                float xv = sxb[d2];
                float4 w0 = Wk4[d2 * 256 + d];
                float4 w1 = Wk4[d2 * 256 + 128 + d];
                a0.x += xv * w0.x; a0.y += xv * w0.y;
                a0.z += xv * w0.z; a0.w += xv * w0.w;
                a1.x += xv * w1.x; a1.y += xv * w1.y;
                a1.z += xv * w1.z; a1.w += xv * w1.w;
            }
            ((float4*)skh)[bb * 256 + d]       = a0;
            ((float4*)skh)[bb * 256 + 128 + d] = a1;
        }
        __syncthreads();

        // c[b,h]: warp w handles combos 2w, 2w+1 of (bb,h)
        {
            int warp = tid >> 5;
            #pragma unroll
            for (int it = 0; it < 2; it++) {
                int combo = warp * 2 + it;         // 0..15
                int cb = combo >> 3, ch = combo & 7;
                float p = 0.f;
                #pragma unroll
                for (int j = 0; j < 4; j++) {
                    int e = lane + 32 * j;
                    p += bq[ch * 128 + e] * skh[cb * 1024 + ch * 128 + e];
                }
                #pragma unroll
                for (int o = 16; o > 0; o >>= 1)
                    p += __shfl_xor_sync(0xffffffffu, p, o);
                if (lane == 0) g_c[(b0 + cb) * 8 + ch] = scale * p + bs[0];
            }
        }

        // u[b,h,d] via smem-tiled Wq (tile 128 rows x 32 cols, pad 33)
        {
            float uacc[8];
            #pragma unroll
            for (int h = 0; h < 8; h++) uacc[h] = 0.f;
            const float4* Wq4 = (const float4*)Wq;
            for (int cc = 0; cc < 32; cc++) {      // h = cc>>2, c0 = (cc&3)*32
                int h = cc >> 2, c0 = (cc & 3) * 32;
                for (int i = tid; i < 1024; i += 256) {
                    int row = i >> 3, g = i & 7;
                    float4 v = Wq4[row * 256 + h * 32 + (c0 >> 2) + g];
                    float* tp = tile + row * 33 + g * 4;
                    tp[0] = v.x; tp[1] = v.y; tp[2] = v.z; tp[3] = v.w;
                }
                __syncthreads();
                const float* kkp  = skh + bb * 1024 + h * 128 + c0;
                const float* trow = tile + d * 33;
                float a = uacc[h];
                #pragma unroll
                for (int e = 0; e < 32; e++) a += trow[e] * kkp[e];
                uacc[h] = a;
                __syncthreads();
            }
            #pragma unroll
            for (int h = 0; h < 8; h++)
                g_u[(b0 + bb) * HE + h * 128 + d] = uacc[h] * scale;
        }
    } else if (blk < 96) {
        // ---------------- role B: M_h tile (16 rows x 128 cols) ----------------
        float* wo_s = s;           // 64 x 128
        float* wv_s = s + 8192;    // 16 x 64
        const int w  = blk - 32;
        const int h  = w >> 3;
        const int r0 = (w & 7) * 16;
        const int d2 = tid & 127, rh = tid >> 7;
        float acc[8];
        #pragma unroll
        for (int j = 0; j < 8; j++) acc[j] = 0.f;
        for (int e0 = 0; e0 < 128; e0 += 64) {
            for (int i = tid; i < 8192; i += 256) {
                int e = i >> 7, dd = i & 127;
                wo_s[i] = Wo[(h * 128 + e0 + e) * DD + dd];
            }
            for (int i = tid; i < 1024; i += 256) {
                int r = i >> 6, e = i & 63;
                wv_s[i] = Wv[(r0 + r) * HE + h * 128 + e0 + e];
            }
            __syncthreads();
            #pragma unroll 8
            for (int e = 0; e < 64; e++) {
                float wo = wo_s[e * 128 + d2];
                #pragma unroll
                for (int j = 0; j < 8; j++)
                    acc[j] += wv_s[(rh * 8 + j) * 64 + e] * wo;
            }
            __syncthreads();
        }
        #pragma unroll
        for (int j = 0; j < 8; j++)
            g_M[(h * 128 + r0 + rh * 8 + j) * DD + d2] = acc[j];
    } else {
        // ---------------- role C: cbias ----------------
        float* red = s;
        const int d2 = tid & 127, half = tid >> 7;
        float acc = half ? 0.f : bo[d2];
        #pragma unroll 8
        for (int k = half * 512; k < half * 512 + 512; k++)
            acc += bv[k] * Wo[k * DD + d2];
        red[tid] = acc;
        __syncthreads();
        if (half == 0) g_cbias[d2] = red[d2] + red[d2 + 128];
    }
}

// ---------------------------------------------------------------------------
// Kernel 2: grid 64 x 256 threads. summary -> softmax -> y -> out.
__global__ __launch_bounds__(256) void k_attn_out(
    const float* __restrict__ x, float* __restrict__ out)
{
    __shared__ float buf[8192];       // phase1: su[1024]; phase3: y partials; phase4: out partials
    __shared__ float sbeta[HH * TT];  // 2048
    __shared__ float sy[HE];          // 1024
    __shared__ float sc[HH];
    const int b = blockIdx.x, tid = threadIdx.x;
    const int lane = tid & 31;

    // load u, c
    for (int i = tid; i < 1024; i += 256) buf[i] = g_u[b * HE + i];
    if (tid < 8) sc[tid] = g_c[b * 8 + tid];
    __syncthreads();

    // phase 1: summary[h, t=tid]
    {
        float acc[8];
        #pragma unroll
        for (int h = 0; h < 8; h++) acc[h] = sc[h];
        const float4* xp = (const float4*)(x + (b * TT + tid) * DD);
        #pragma unroll 4
        for (int d4 = 0; d4 < 32; d4++) {
            float4 xv = xp[d4];
            #pragma unroll
            for (int h = 0; h < 8; h++) {
                float4 uv = ((const float4*)(buf + h * 128))[d4];
                acc[h] += xv.x * uv.x + xv.y * uv.y + xv.z * uv.z + xv.w * uv.w;
            }
        }
        #pragma unroll
        for (int h = 0; h < 8; h++) sbeta[h * TT + tid] = acc[h];
    }
    __syncthreads();

    // phase 2: softmax over t (warp = head)
    {
        int h = tid >> 5;
        float v[8];
        float m = -1e30f;
        #pragma unroll
        for (int i = 0; i < 8; i++) {
            v[i] = sbeta[h * TT + lane + 32 * i];
            m = fmaxf(m, v[i]);
        }
        #pragma unroll
        for (int o = 16; o > 0; o >>= 1) m = fmaxf(m, __shfl_xor_sync(0xffffffffu, m, o));
        float ssum = 0.f;
        #pragma unroll
        for (int i = 0; i < 8; i++) { v[i] = __expf(v[i] - m); ssum += v[i]; }
        #pragma unroll
        for (int o = 16; o > 0; o >>= 1) ssum += __shfl_xor_sync(0xffffffffu, ssum, o);
        float inv = 1.f / ssum;
        #pragma unroll
        for (int i = 0; i < 8; i++) sbeta[h * TT + lane + 32 * i] = v[i] * inv;
    }
    __syncthreads();

    // phase 3: y partials — thread (tq=tid>>5, lane): d-range lane*4..+3, t-range tq*32..+31
    {
        int tq = tid >> 5;
        float4 a[8];
        #pragma unroll
        for (int h = 0; h < 8; h++) a[h] = make_float4(0.f, 0.f, 0.f, 0.f);
        const float4* x4 = (const float4*)x;
        int base = (b * TT + tq * 32) * 32 + lane;
        #pragma unroll 4
        for (int t = 0; t < 32; t++) {
            float4 xv = x4[base + t * 32];
            int tt = tq * 32 + t;
            #pragma unroll
            for (int h = 0; h < 8; h++) {
                float bta = sbeta[h * TT + tt];
                a[h].x += bta * xv.x; a[h].y += bta * xv.y;
                a[h].z += bta * xv.z; a[h].w += bta * xv.w;
            }
        }
        // buf reads (su) all completed before phase-2 sync; safe to overwrite
        #pragma unroll
        for (int h = 0; h < 8; h++)
            ((float4*)buf)[tq * 256 + h * 32 + lane] = a[h];
    }
    __syncthreads();

    // combine 8 t-partials -> sy
    for (int i = tid; i < 1024; i += 256) {
        float v = 0.f;
        #pragma unroll
        for (int tq = 0; tq < 8; tq++) v += buf[tq * 1024 + i];
        sy[i] = v;
    }
    __syncthreads();

    // phase 4: out[b,d2] = sy . M[:,d2] + cbias  (thread: kq=tid>>5, d2 = lane*4..+3)
    {
        int kq = tid >> 5;
        const float4* M4 = (const float4*)g_M;
        float4 a = make_float4(0.f, 0.f, 0.f, 0.f);
        #pragma unroll 8
        for (int k = kq * 128; k < kq * 128 + 128; k++) {
            float yk = sy[k];
            float4 mv = M4[k * 32 + lane];
            a.x += yk * mv.x; a.y += yk * mv.y;
            a.z += yk * mv.z; a.w += yk * mv.w;
        }
        ((float4*)buf)[kq * 32 + lane] = a;
    }
    __syncthreads();
    if (tid < 128) {
        float o = g_cbias[tid];
        #pragma unroll
        for (int kq = 0; kq < 8; kq++) o += buf[kq * 128 + tid];
        out[b * DD + tid] = o;
    }
}

// ---------------------------------------------------------------------------
extern "C" void kernel_launch(void* const* d_in, const int* in_sizes, int n_in,
                              void* d_out, int out_size) {
    const float* x  = (const float*)d_in[0];
    const float* Wq = (const float*)d_in[1];
    const float* bq = (const float*)d_in[2];
    const float* Wk = (const float*)d_in[3];
    const float* bk = (const float*)d_in[4];
    const float* Wv = (const float*)d_in[5];
    const float* bv = (const float*)d_in[6];
    const float* Ws = (const float*)d_in[7];
    const float* bs = (const float*)d_in[8];
    const float* Wo = (const float*)d_in[9];
    const float* bo = (const float*)d_in[10];
    float* out = (float*)d_out;

    k_pre<<<97, 256>>>(x, Ws, Wk, bk, Wq, bq, bs, Wv, bv, Wo, bo);
    k_attn_out<<<64, 256>>>(x, out);
}

// round 3
// speedup vs baseline: 2.0324x; 1.4393x over previous
#include <cuda_runtime.h>

// Temporal_Attention — fully weight-space-collapsed.
// B=64, T=256, D=128, H=8, E=128.  out[B,D] fp32.
//
//  Weight-only:  G'[h,d',d] = scale * sum_e Wk[d',he] Wq[d,he]
//                ub'[h,d]   = scale * sum_e Wq[d,he] bk[he]
//                gb'[h,d']  = scale * sum_e Wk[d',he] bq[he]
//                dq'[h]     = scale * sum_e bk[he] bq[he]
//                M[h,d1,d2] = sum_e Wv[d1,he] Wo[he,d2]
//                cbias      = bo + sum_k bv[k] Wo[k,:]
//  Data path:    xs[b] = sum_t Ws[t] x[b,t] ;  S = sum Ws
//                u[b,h,d] = xs[b].G'[h,:,d] + S ub'[h,d]
//                c[b,h]   = xs[b].gb'[h] + S dq'[h] + bs
//                beta = softmax_t( x[b,t].u[b,h] + c[b,h] )
//                y[b,h,d] = sum_t beta x[b,t,d]
//                out[b]   = y[b] @ Mflat + cbias

#define BB 64
#define TT 256
#define DD 128
#define HH 8
#define HE 1024
#define SCALE 0.088388347648318447f

static __device__ __align__(16) float g_xs[BB * DD];
static __device__ float g_S;
static __device__ __align__(16) float g_G[HH * DD * DD];
static __device__ __align__(16) float g_ub[HH * DD];
static __device__ __align__(16) float g_gb[HH * DD];
static __device__ float g_dqs[HH];
static __device__ __align__(16) float g_M[HE * DD];
static __device__ __align__(16) float g_cbp[8 * DD];
static __device__ __align__(16) float g_u[BB * HE];
static __device__ float g_c[BB * HH];
static __device__ __align__(16) float g_y[BB * HE];

// ---- packed f32x2 helpers -------------------------------------------------
__device__ __forceinline__ void ffma2(unsigned long long& d,
                                      unsigned long long a, unsigned long long b) {
    asm("fma.rn.f32x2 %0, %1, %2, %0;" : "+l"(d) : "l"(a), "l"(b));
}
__device__ __forceinline__ unsigned long long pk2(float x, float y) {
    unsigned long long r;
    asm("mov.b64 %0, {%1, %2};" : "=l"(r) : "f"(x), "f"(y));
    return r;
}
__device__ __forceinline__ float2 upk2(unsigned long long v) {
    float lo, hi;
    asm("mov.b64 {%0, %1}, %2;" : "=f"(lo), "=f"(hi) : "l"(v));
    return make_float2(lo, hi);
}
__device__ __forceinline__ float dot4(float4 a, float4 b) {
    return a.x * b.x + a.y * b.y + a.z * b.z + a.w * b.w;
}

// ===========================================================================
// K1: grid 209 x 256.  roles: xs(0-63) | G(64-127) | M(128-191) | gb(192-199)
//                             | cbias(200-207) | misc(208)
__global__ __launch_bounds__(256) void k_pre(
    const float* __restrict__ x,  const float* __restrict__ Ws,
    const float* __restrict__ Wk, const float* __restrict__ bk,
    const float* __restrict__ Wq, const float* __restrict__ bq,
    const float* __restrict__ Wv, const float* __restrict__ bv,
    const float* __restrict__ Wo, const float* __restrict__ bo)
{
    __shared__ __align__(16) float s[12288];   // 48 KB
    const int blk = blockIdx.x, tid = threadIdx.x;

    if (blk < 64) {
        // ------------- xs role: one batch -------------
        const int b = blk, c = tid & 31, tg = tid >> 5;
        const float4* x4 = (const float4*)x;
        float4 acc = make_float4(0.f, 0.f, 0.f, 0.f);
        #pragma unroll 8
        for (int t = tg * 32; t < tg * 32 + 32; t++) {
            float w = __ldg(Ws + t);
            float4 xv = x4[(b * TT + t) * 32 + c];
            acc.x += w * xv.x; acc.y += w * xv.y;
            acc.z += w * xv.z; acc.w += w * xv.w;
        }
        float4* p4 = (float4*)s;
        p4[tg * 32 + c] = acc;
        __syncthreads();
        if (tid < 32) {
            float4 r = p4[tid];
            #pragma unroll
            for (int g = 1; g < 8; g++) {
                float4 v = p4[g * 32 + tid];
                r.x += v.x; r.y += v.y; r.z += v.z; r.w += v.w;
            }
            ((float4*)g_xs)[b * 32 + tid] = r;
        }
    } else if (blk < 128) {
        // ------------- G role: G'[h, r0..r0+15, :] (+ub on rt==0) -------------
        const int w = blk - 64, h = w >> 3, rt = w & 7, r0 = rt * 16;
        const int d2 = tid & 127, rg = tid >> 7;
        float4* wq4s = (float4*)s;            // [128][17] float4 (pad 68 floats)
        float4* wk4s = (float4*)(s + 8704);   // [16][16]
        float4* bk4s = (float4*)(s + 9728);   // [16]
        const float4* Wq4 = (const float4*)Wq;
        const float4* Wk4 = (const float4*)Wk;
        float acc[8];
        #pragma unroll
        for (int j = 0; j < 8; j++) acc[j] = 0.f;
        float ubacc = 0.f;
        for (int e0 = 0; e0 < 2; e0++) {           // e-chunks of 64
            #pragma unroll
            for (int k = 0; k < 8; k++) {
                int i = tid + k * 256;
                int dd = i >> 4, eq = i & 15;
                wq4s[dd * 17 + eq] = Wq4[dd * 256 + h * 32 + e0 * 16 + eq];
            }
            {
                int r = tid >> 4, eq = tid & 15;
                wk4s[r * 16 + eq] = Wk4[(r0 + r) * 256 + h * 32 + e0 * 16 + eq];
            }
            if (rt == 0 && tid < 16)
                bk4s[tid] = ((const float4*)bk)[h * 32 + e0 * 16 + tid];
            __syncthreads();
            #pragma unroll 4
            for (int e4 = 0; e4 < 16; e4++) {
                float4 q4 = wq4s[d2 * 17 + e4];
                #pragma unroll
                for (int j = 0; j < 8; j++)
                    acc[j] += dot4(q4, wk4s[(rg * 8 + j) * 16 + e4]);
                if (rt == 0 && rg == 0) ubacc += dot4(q4, bk4s[e4]);
            }
            __syncthreads();
        }
        #pragma unroll
        for (int j = 0; j < 8; j++)
            g_G[h * 16384 + (r0 + rg * 8 + j) * DD + d2] = SCALE * acc[j];
        if (rt == 0 && rg == 0) g_ub[h * DD + d2] = SCALE * ubacc;
    } else if (blk < 192) {
        // ------------- M role: M[h, r0..r0+15, :] -------------
        const int w = blk - 128, h = w >> 3, r0 = (w & 7) * 16;
        const int d2 = tid & 127, rh = tid >> 7;
        float* wo_s = s;            // 64 x 128
        float* wv_s = s + 8192;     // 16 x 64
        float acc[8];
        #pragma unroll
        for (int j = 0; j < 8; j++) acc[j] = 0.f;
        for (int e0 = 0; e0 < 128; e0 += 64) {
            for (int i = tid; i < 8192; i += 256) {
                int e = i >> 7, dd = i & 127;
                wo_s[i] = Wo[(h * 128 + e0 + e) * DD + dd];
            }
            for (int i = tid; i < 1024; i += 256) {
                int r = i >> 6, e = i & 63;
                wv_s[i] = Wv[(r0 + r) * HE + h * 128 + e0 + e];
            }
            __syncthreads();
            #pragma unroll 8
            for (int e = 0; e < 64; e++) {
                float wo = wo_s[e * 128 + d2];
                #pragma unroll
                for (int j = 0; j < 8; j++)
                    acc[j] += wv_s[(rh * 8 + j) * 64 + e] * wo;
            }
            __syncthreads();
        }
        #pragma unroll
        for (int j = 0; j < 8; j++)
            g_M[(h * 128 + r0 + rh * 8 + j) * DD + d2] = acc[j];
    } else if (blk < 200) {
        // ------------- gb role: gb'[h, :] -------------
        const int h = blk - 192, eq = tid & 31, dg = tid >> 5;
        float4 bqv = ((const float4*)bq)[h * 32 + eq];
        const float4* Wk4 = (const float4*)Wk;
        #pragma unroll
        for (int i = 0; i < 16; i++) {
            int dd = dg * 16 + i;
            float p = dot4(Wk4[dd * 256 + h * 32 + eq], bqv);
            #pragma unroll
            for (int o = 16; o > 0; o >>= 1)
                p += __shfl_xor_sync(0xffffffffu, p, o);
            if (eq == 0) g_gb[h * DD + dd] = SCALE * p;
        }
    } else if (blk < 208) {
        // ------------- cbias partial: k-slice p -------------
        const int p = blk - 200, d2 = tid & 127, kh = tid >> 7;
        float acc = 0.f;
        #pragma unroll 8
        for (int i = 0; i < 64; i++) {
            int k = p * 128 + kh * 64 + i;
            acc += __ldg(bv + k) * Wo[k * DD + d2];
        }
        s[tid] = acc;
        __syncthreads();
        if (kh == 0)
            g_cbp[p * DD + d2] = s[d2] + s[128 + d2] + (p == 0 ? bo[d2] : 0.f);
    } else {
        // ------------- misc: S, dq' -------------
        s[tid] = Ws[tid];
        {
            int h = tid >> 5, lane = tid & 31;
            float p = dot4(((const float4*)bk)[h * 32 + lane],
                           ((const float4*)bq)[h * 32 + lane]);
            #pragma unroll
            for (int o = 16; o > 0; o >>= 1)
                p += __shfl_xor_sync(0xffffffffu, p, o);
            if (lane == 0) g_dqs[h] = SCALE * p;
        }
        __syncthreads();
        for (int st = 128; st > 0; st >>= 1) {
            if (tid < st) s[tid] += s[tid + st];
            __syncthreads();
        }
        if (tid == 0) g_S = s[0];
    }
}

// ===========================================================================
// K3: u[b, h*128+d] = xs[b].G'[h,:,d] + S*ub'[h,d].  grid 64 = (h, dtile16).
__global__ __launch_bounds__(256) void k_u(void) {
    __shared__ __align__(16) float xs_s[64 * 132];  // pad-132 rows
    __shared__ __align__(16) float G_s[128 * 16];
    const int h = blockIdx.x >> 3, dt = blockIdx.x & 7;
    const int tid = threadIdx.x;
    {
        float4* xs4 = (float4*)xs_s;
        const float4* gx4 = (const float4*)g_xs;
        #pragma unroll
        for (int k = 0; k < 8; k++) {
            int i = tid + k * 256;
            int bb = i >> 5, c = i & 31;
            xs4[bb * 33 + c] = gx4[bb * 32 + c];
        }
        float4* G4s = (float4*)G_s;
        const float4* gG4 = (const float4*)g_G;
        #pragma unroll
        for (int k = 0; k < 2; k++) {
            int i = tid + k * 256;
            int dp = i >> 2, q = i & 3;
            G4s[dp * 4 + q] = gG4[h * 4096 + dp * 32 + dt * 4 + q];
        }
    }
    __syncthreads();
    const int dq = tid & 3, b = tid >> 2;
    const float4* G4s = (const float4*)G_s;
    float4 acc = make_float4(0.f, 0.f, 0.f, 0.f);
    #pragma unroll 8
    for (int dp = 0; dp < 128; dp++) {
        float xv = xs_s[b * 132 + dp];
        float4 gv = G4s[dp * 4 + dq];
        acc.x += xv * gv.x; acc.y += xv * gv.y;
        acc.z += xv * gv.z; acc.w += xv * gv.w;
    }
    float S = g_S;
    float4 ubv = ((const float4*)g_ub)[h * 32 + dt * 4 + dq];
    acc.x += S * ubv.x; acc.y += S * ubv.y;
    acc.z += S * ubv.z; acc.w += S * ubv.w;
    ((float4*)g_u)[b * 256 + h * 32 + dt * 4 + dq] = acc;
}

// ===========================================================================
// K4: attention per batch.  grid 64 x 512.
__global__ __launch_bounds__(512) void k_attn(
    const float* __restrict__ x, const float* __restrict__ bs)
{
    __shared__ __align__(16) float tile[64 * 132];   // 33.8 KB
    __shared__ __align__(16) float su[1024];
    __shared__ __align__(16) float sbeta[TT * 8];    // [t][h]
    __shared__ float sc[8];
    const int b = blockIdx.x, tid = threadIdx.x;

    // c[b,h]
    if (tid < 256) {
        int h = tid >> 5, lane = tid & 31;
        float p = dot4(((const float4*)g_xs)[b * 32 + lane],
                       ((const float4*)g_gb)[h * 32 + lane]);
        #pragma unroll
        for (int o = 16; o > 0; o >>= 1)
            p += __shfl_xor_sync(0xffffffffu, p, o);
        if (lane == 0) sc[h] = p + g_S * g_dqs[h] + bs[0];
    }
    for (int i = tid; i < 1024; i += 512) su[i] = g_u[b * HE + i];

    const float4* x4 = (const float4*)x;
    float4* tile4 = (float4*)tile;

    // ---- pass A: summary ----
    const int tl = tid & 63, hg = tid >> 6;
    for (int ti = 0; ti < 4; ti++) {
        const int t0 = ti * 64;
        #pragma unroll
        for (int k = 0; k < 4; k++) {
            int j = tid + k * 512;
            int row = j >> 5, col = j & 31;
            tile4[row * 33 + col] = x4[(b * TT + t0 + row) * 32 + col];
        }
        __syncthreads();
        const ulonglong2* tl2 = (const ulonglong2*)tile;
        const ulonglong2* su2 = (const ulonglong2*)su;
        unsigned long long a0 = 0ull, a1 = 0ull;
        #pragma unroll 8
        for (int e4 = 0; e4 < 32; e4++) {
            ulonglong2 xv = tl2[tl * 33 + e4];
            ulonglong2 uv = su2[hg * 32 + e4];
            ffma2(a0, xv.x, uv.x);
            ffma2(a1, xv.y, uv.y);
        }
        float2 fa = upk2(a0), fb = upk2(a1);
        sbeta[(t0 + tl) * 8 + hg] = fa.x + fa.y + fb.x + fb.y + sc[hg];
        __syncthreads();
    }

    // ---- softmax over t, warp per head ----
    if (tid < 256) {
        int h = tid >> 5, lane = tid & 31;
        float v[8];
        float m = -1e30f;
        #pragma unroll
        for (int i = 0; i < 8; i++) {
            v[i] = sbeta[(lane + 32 * i) * 8 + h];
            m = fmaxf(m, v[i]);
        }
        #pragma unroll
        for (int o = 16; o > 0; o >>= 1)
            m = fmaxf(m, __shfl_xor_sync(0xffffffffu, m, o));
        float ssum = 0.f;
        #pragma unroll
        for (int i = 0; i < 8; i++) { v[i] = __expf(v[i] - m); ssum += v[i]; }
        #pragma unroll
        for (int o = 16; o > 0; o >>= 1)
            ssum += __shfl_xor_sync(0xffffffffu, ssum, o);
        float inv = 1.f / ssum;
        #pragma unroll
        for (int i = 0; i < 8; i++)
            sbeta[(lane + 32 * i) * 8 + h] = v[i] * inv;
    }
    __syncthreads();

    // ---- pass C: y[h,d] = sum_t beta[t,h] x[t,d]  (h-pairs packed) ----
    const int d = tid & 127, hp = tid >> 7;     // hp in 0..3 -> heads 2hp, 2hp+1
    unsigned long long acc = 0ull;
    for (int ti = 0; ti < 4; ti++) {
        const int t0 = ti * 64;
        #pragma unroll
        for (int k = 0; k < 4; k++) {
            int j = tid + k * 512;
            int row = j >> 5, col = j & 31;
            tile4[row * 33 + col] = x4[(b * TT + t0 + row) * 32 + col];
        }
        __syncthreads();
        #pragma unroll 8
        for (int t = 0; t < 64; t++) {
            float xv = tile[t * 132 + d];
            unsigned long long bt =
                *(const unsigned long long*)&sbeta[(t0 + t) * 8 + hp * 2];
            ffma2(acc, bt, pk2(xv, xv));
        }
        __syncthreads();
    }
    float2 yv = upk2(acc);
    g_y[b * HE + (hp * 2) * 128 + d]     = yv.x;
    g_y[b * HE + (hp * 2 + 1) * 128 + d] = yv.y;
}

// ===========================================================================
// K5: out[b,:] = y[b] @ Mflat + cbias.  grid 64 = (b-pair, d-half).
__global__ __launch_bounds__(256) void k_out(float* __restrict__ out) {
    __shared__ __align__(16) float y_s[2 * HE];   // 8 KB
    __shared__ __align__(16) float cb_s[64];
    __shared__ __align__(16) float part[2048];    // 512 float4
    const int bp = blockIdx.x >> 1, dh = blockIdx.x & 1;
    const int tid = threadIdx.x;
    const int b0 = bp * 2;

    for (int i = tid; i < 2048; i += 256) y_s[i] = g_y[b0 * HE + i];
    if (tid < 64) {
        float cb = 0.f;
        #pragma unroll
        for (int p = 0; p < 8; p++) cb += g_cbp[p * DD + dh * 64 + tid];
        cb_s[tid] = cb;
    }
    __syncthreads();

    const int q = tid & 15, kg = tid >> 4;
    const ulonglong2* M2 = (const ulonglong2*)g_M;
    unsigned long long a0l = 0, a0h = 0, a1l = 0, a1h = 0;
    #pragma unroll 4
    for (int kk = 0; kk < 64; kk++) {
        int k = kg * 64 + kk;
        ulonglong2 m = M2[k * 16 + dh * 8 + q >> 1 << 1 | (q & 1)];
        // (note: k*32 float4 per row; dh*16 + q float4 -> /2 for ulonglong2? use direct:)
        (void)m;
        ulonglong2 mv = ((const ulonglong2*)g_M)[(k * 32 + dh * 16 + q) >> 1];
        // k*32+dh*16+q is a float4 index; ulonglong2 == float4 (16B) so index matches:
        mv = ((const ulonglong2*)g_M)[k * 32 + dh * 16 + q];
        unsigned long long y0 = pk2(y_s[k], y_s[k]);
        unsigned long long y1 = pk2(y_s[HE + k], y_s[HE + k]);
        ffma2(a0l, mv.x, y0); ffma2(a0h, mv.y, y0);
        ffma2(a1l, mv.x, y1); ffma2(a1h, mv.y, y1);
    }
    float2 p0l = upk2(a0l), p0h = upk2(a0h), p1l = upk2(a1l), p1h = upk2(a1h);
    float4* part4 = (float4*)part;
    part4[(kg * 16 + q) * 2 + 0] = make_float4(p0l.x, p0l.y, p0h.x, p0h.y);
    part4[(kg * 16 + q) * 2 + 1] = make_float4(p1l.x, p1l.y, p1h.x, p1h.y);
    __syncthreads();

    if (tid < 32) {
        int qq = tid & 15, bb = tid >> 4;
        float4 r = make_float4(0.f, 0.f, 0.f, 0.f);
        #pragma unroll
        for (int g = 0; g < 16; g++) {
            float4 v = part4[(g * 16 + qq) * 2 + bb];
            r.x += v.x; r.y += v.y; r.z += v.z; r.w += v.w;
        }
        float4 cb = ((const float4*)cb_s)[qq];
        r.x += cb.x; r.y += cb.y; r.z += cb.z; r.w += cb.w;
        ((float4*)out)[(b0 + bb) * 32 + dh * 16 + qq] = r;
    }
}

// ===========================================================================
extern "C" void kernel_launch(void* const* d_in, const int* in_sizes, int n_in,
                              void* d_out, int out_size) {
    const float* x  = (const float*)d_in[0];
    const float* Wq = (const float*)d_in[1];
    const float* bq = (const float*)d_in[2];
    const float* Wk = (const float*)d_in[3];
    const float* bk = (const float*)d_in[4];
    const float* Wv = (const float*)d_in[5];
    const float* bv = (const float*)d_in[6];
    const float* Ws = (const float*)d_in[7];
    const float* bs = (const float*)d_in[8];
    const float* Wo = (const float*)d_in[9];
    const float* bo = (const float*)d_in[10];
    float* out = (float*)d_out;

    k_pre<<<209, 256>>>(x, Ws, Wk, bk, Wq, bq, Wv, bv, Wo, bo);
    k_u<<<64, 256>>>();
    k_attn<<<64, 512>>>(x, bs);
    k_out<<<64, 256>>>(out);
}

// round 4
// speedup vs baseline: 2.6360x; 1.2970x over previous
#include <cuda_runtime.h>

// Temporal_Attention — weight-space-collapsed, 2 kernels.
// B=64, T=256, D=128, H=8, E=128.  out[B,D] fp32.
//
//  K1 (weights + xs):
//    G'[h,dp,d] = scale * sum_e Wk[dp,he] Wq[d,he]
//    ub'[h,d]   = scale * sum_e Wq[d,he] bk[he]
//    gb'[h,dp]  = scale * sum_e Wk[dp,he] bq[he]
//    dq'[h]     = scale * sum_e bk[he] bq[he]
//    M[hd,d2]   = sum_e Wv[d1,he] Wo[he,d2] ; cbias partials
//    xs[b] = sum_t Ws[t] x[b,t] ; S = sum Ws
//  K2 (per batch, fused):
//    u[h,d] = xs.G'[h,:,d] + S ub'  ;  c[h] = xs.gb'[h] + S dq' + bs
//    beta = softmax_t( x[t].u[h] + c[h] )
//    y[h,d] = sum_t beta x[t,d]
//    out = y @ M + cbias

#define BB 64
#define TT 256
#define DD 128
#define HH 8
#define HE 1024
#define SCALE 0.088388347648318447f

static __device__ __align__(16) float g_xs[BB * DD];
static __device__ float g_S;
static __device__ __align__(16) float g_G[HH * DD * DD];
static __device__ __align__(16) float g_ub[HH * DD];
static __device__ __align__(16) float g_gb[HH * DD];
static __device__ float g_dqs[HH];
static __device__ __align__(16) float g_M[HE * DD];
static __device__ __align__(16) float g_cbp[8 * DD];

// ---- packed f32x2 helpers -------------------------------------------------
__device__ __forceinline__ void ffma2(unsigned long long& d,
                                      unsigned long long a, unsigned long long b) {
    asm("fma.rn.f32x2 %0, %1, %2, %0;" : "+l"(d) : "l"(a), "l"(b));
}
__device__ __forceinline__ unsigned long long pk2(float x, float y) {
    unsigned long long r;
    asm("mov.b64 %0, {%1, %2};" : "=l"(r) : "f"(x), "f"(y));
    return r;
}
__device__ __forceinline__ float2 upk2(unsigned long long v) {
    float lo, hi;
    asm("mov.b64 {%0, %1}, %2;" : "=f"(lo), "=f"(hi) : "l"(v));
    return make_float2(lo, hi);
}
__device__ __forceinline__ float dot4(float4 a, float4 b) {
    return a.x * b.x + a.y * b.y + a.z * b.z + a.w * b.w;
}

// ===========================================================================
// K1: grid 209 x 256.  roles: xs(0-63) | G(64-127) | M(128-191) | gb(192-199)
//                             | cbias(200-207) | misc(208)
__global__ __launch_bounds__(256) void k_pre(
    const float* __restrict__ x,  const float* __restrict__ Ws,
    const float* __restrict__ Wk, const float* __restrict__ bk,
    const float* __restrict__ Wq, const float* __restrict__ bq,
    const float* __restrict__ Wv, const float* __restrict__ bv,
    const float* __restrict__ Wo, const float* __restrict__ bo)
{
    __shared__ __align__(16) float s[12288];   // 48 KB
    const int blk = blockIdx.x, tid = threadIdx.x;

    if (blk < 64) {
        // ------------- xs role: one batch -------------
        const int b = blk, c = tid & 31, tg = tid >> 5;
        const float4* x4 = (const float4*)x;
        float4 acc = make_float4(0.f, 0.f, 0.f, 0.f);
        #pragma unroll 16
        for (int t = tg * 32; t < tg * 32 + 32; t++) {
            float w = __ldg(Ws + t);
            float4 xv = x4[(b * TT + t) * 32 + c];
            acc.x += w * xv.x; acc.y += w * xv.y;
            acc.z += w * xv.z; acc.w += w * xv.w;
        }
        float4* p4 = (float4*)s;
        p4[tg * 32 + c] = acc;
        __syncthreads();
        if (tid < 32) {
            float4 r = p4[tid];
            #pragma unroll
            for (int g = 1; g < 8; g++) {
                float4 v = p4[g * 32 + tid];
                r.x += v.x; r.y += v.y; r.z += v.z; r.w += v.w;
            }
            ((float4*)g_xs)[b * 32 + tid] = r;
        }
    } else if (blk < 128) {
        // ------------- G role: G'[h, r0..r0+15, :] (+ub on rt==0) -------------
        const int w = blk - 64, h = w >> 3, rt = w & 7, r0 = rt * 16;
        const int d2 = tid & 127, rg = tid >> 7;
        float4* wq4s = (float4*)s;            // [128][17] float4
        float4* wk4s = (float4*)(s + 8704);   // [16][16]
        float4* bk4s = (float4*)(s + 9728);   // [16]
        const float4* Wq4 = (const float4*)Wq;
        const float4* Wk4 = (const float4*)Wk;
        float acc[8];
        #pragma unroll
        for (int j = 0; j < 8; j++) acc[j] = 0.f;
        float ubacc = 0.f;
        for (int e0 = 0; e0 < 2; e0++) {           // e-chunks of 64
            #pragma unroll
            for (int k = 0; k < 8; k++) {
                int i = tid + k * 256;
                int dd = i >> 4, eq = i & 15;
                wq4s[dd * 17 + eq] = Wq4[dd * 256 + h * 32 + e0 * 16 + eq];
            }
            {
                int r = tid >> 4, eq = tid & 15;
                wk4s[r * 16 + eq] = Wk4[(r0 + r) * 256 + h * 32 + e0 * 16 + eq];
            }
            if (rt == 0 && tid < 16)
                bk4s[tid] = ((const float4*)bk)[h * 32 + e0 * 16 + tid];
            __syncthreads();
            #pragma unroll 4
            for (int e4 = 0; e4 < 16; e4++) {
                float4 q4 = wq4s[d2 * 17 + e4];
                #pragma unroll
                for (int j = 0; j < 8; j++)
                    acc[j] += dot4(q4, wk4s[(rg * 8 + j) * 16 + e4]);
                if (rt == 0 && rg == 0) ubacc += dot4(q4, bk4s[e4]);
            }
            __syncthreads();
        }
        #pragma unroll
        for (int j = 0; j < 8; j++)
            g_G[h * 16384 + (r0 + rg * 8 + j) * DD + d2] = SCALE * acc[j];
        if (rt == 0 && rg == 0) g_ub[h * DD + d2] = SCALE * ubacc;
    } else if (blk < 192) {
        // ------------- M role: M[h, r0..r0+15, :] -------------
        const int w = blk - 128, h = w >> 3, r0 = (w & 7) * 16;
        const int d2 = tid & 127, rh = tid >> 7;
        float* wo_s = s;            // 64 x 128
        float* wv_s = s + 8192;     // 16 x 64
        float acc[8];
        #pragma unroll
        for (int j = 0; j < 8; j++) acc[j] = 0.f;
        for (int e0 = 0; e0 < 128; e0 += 64) {
            for (int i = tid; i < 8192; i += 256) {
                int e = i >> 7, dd = i & 127;
                wo_s[i] = Wo[(h * 128 + e0 + e) * DD + dd];
            }
            for (int i = tid; i < 1024; i += 256) {
                int r = i >> 6, e = i & 63;
                wv_s[i] = Wv[(r0 + r) * HE + h * 128 + e0 + e];
            }
            __syncthreads();
            #pragma unroll 8
            for (int e = 0; e < 64; e++) {
                float wo = wo_s[e * 128 + d2];
                #pragma unroll
                for (int j = 0; j < 8; j++)
                    acc[j] += wv_s[(rh * 8 + j) * 64 + e] * wo;
            }
            __syncthreads();
        }
        #pragma unroll
        for (int j = 0; j < 8; j++)
            g_M[(h * 128 + r0 + rh * 8 + j) * DD + d2] = acc[j];
    } else if (blk < 200) {
        // ------------- gb role: gb'[h, :] -------------
        const int h = blk - 192, eq = tid & 31, dg = tid >> 5;
        float4 bqv = ((const float4*)bq)[h * 32 + eq];
        const float4* Wk4 = (const float4*)Wk;
        #pragma unroll
        for (int i = 0; i < 16; i++) {
            int dd = dg * 16 + i;
            float p = dot4(Wk4[dd * 256 + h * 32 + eq], bqv);
            #pragma unroll
            for (int o = 16; o > 0; o >>= 1)
                p += __shfl_xor_sync(0xffffffffu, p, o);
            if (eq == 0) g_gb[h * DD + dd] = SCALE * p;
        }
    } else if (blk < 208) {
        // ------------- cbias partial: k-slice p -------------
        const int p = blk - 200, d2 = tid & 127, kh = tid >> 7;
        float acc = 0.f;
        #pragma unroll 8
        for (int i = 0; i < 64; i++) {
            int k = p * 128 + kh * 64 + i;
            acc += __ldg(bv + k) * Wo[k * DD + d2];
        }
        s[tid] = acc;
        __syncthreads();
        if (kh == 0)
            g_cbp[p * DD + d2] = s[d2] + s[128 + d2] + (p == 0 ? bo[d2] : 0.f);
    } else {
        // ------------- misc: S, dq' -------------
        s[tid] = Ws[tid];
        {
            int h = tid >> 5, lane = tid & 31;
            float p = dot4(((const float4*)bk)[h * 32 + lane],
                           ((const float4*)bq)[h * 32 + lane]);
            #pragma unroll
            for (int o = 16; o > 0; o >>= 1)
                p += __shfl_xor_sync(0xffffffffu, p, o);
            if (lane == 0) g_dqs[h] = SCALE * p;
        }
        __syncthreads();
        for (int st = 128; st > 0; st >>= 1) {
            if (tid < st) s[tid] += s[tid + st];
            __syncthreads();
        }
        if (tid == 0) g_S = s[0];
    }
}

// ===========================================================================
// K2: one block per batch.  grid 64 x 512, 165920 B dynamic smem.
//   smem layout (float offsets):
//     sxT   [128][257]  @ 0       (x transposed, conflict-free pad)
//     suT   [128][10]   @ 32896   (u transposed, h-pairs 8B-aligned)
//     sbeta [256][8]    @ 34176
//     sy    [1024]      @ 36224
//     spart [4096]      @ 37248   (phase-local partials, reused)
//     sxs   [128]       @ 41344
//     sc    [8]         @ 41472
#define SXT_OFF   0
#define SUT_OFF   32896
#define SBETA_OFF 34176
#define SY_OFF    36224
#define SPART_OFF 37248
#define SXS_OFF   41344
#define SC_OFF    41472
#define SMEM_K2_FLOATS 41480

__global__ __launch_bounds__(512) void k_main(
    const float* __restrict__ x, const float* __restrict__ bs,
    float* __restrict__ out)
{
    extern __shared__ __align__(16) float sm[];
    float* sxT   = sm + SXT_OFF;
    float* suT   = sm + SUT_OFF;
    float* sbeta = sm + SBETA_OFF;
    float* sy    = sm + SY_OFF;
    float* spart = sm + SPART_OFF;
    float* sxs   = sm + SXS_OFF;
    float* sc    = sm + SC_OFF;
    const int b = blockIdx.x, tid = threadIdx.x;

    // ---- phase 0: xs -> smem, c[h] -> sc, x_b -> sxT (transposed) ----
    if (tid < 128) sxs[tid] = g_xs[b * DD + tid];
    if (tid < 256) {
        int h = tid >> 5, lane = tid & 31;
        float p = dot4(((const float4*)g_xs)[b * 32 + lane],
                       ((const float4*)g_gb)[h * 32 + lane]);
        #pragma unroll
        for (int o = 16; o > 0; o >>= 1)
            p += __shfl_xor_sync(0xffffffffu, p, o);
        if (lane == 0) sc[h] = p + g_S * g_dqs[h] + bs[0];
    }
    {
        const int d = tid & 127, tg = tid >> 7;
        const float* xb = x + b * TT * DD;
        #pragma unroll 8
        for (int k = 0; k < 64; k++) {
            int t = k * 4 + tg;
            sxT[d * 257 + t] = xb[t * DD + d];   // coalesced LDG, conflict-free STS
        }
    }
    __syncthreads();

    // ---- phase 1: u partials (float4-coalesced G reads) ----
    {
        const int idx = tid & 255, h = idx >> 5, q = idx & 31, half = tid >> 8;
        const float4* G4 = (const float4*)(g_G + h * 16384);
        float4 acc = make_float4(0.f, 0.f, 0.f, 0.f);
        #pragma unroll 8
        for (int dp = half * 64; dp < half * 64 + 64; dp++) {
            float xv = sxs[dp];
            float4 gv = G4[dp * 32 + q];
            acc.x += xv * gv.x; acc.y += xv * gv.y;
            acc.z += xv * gv.z; acc.w += xv * gv.w;
        }
        ((float4*)spart)[half * 256 + h * 32 + q] = acc;
    }
    __syncthreads();
    {
        float S = g_S;
        #pragma unroll
        for (int k = 0; k < 2; k++) {
            int i = tid + k * 512;               // hd = h*128+d
            int h = i >> 7, d = i & 127;
            suT[d * 10 + h] = spart[i] + spart[1024 + i] + S * g_ub[i];
        }
    }
    __syncthreads();

    // ---- phase 2: summary[t,h] (f32x2, broadcast u reads) ----
    {
        const int t = tid & 255, hh = tid >> 8;   // heads hh*4 .. hh*4+3
        unsigned long long a0 = 0ull, a1 = 0ull;
        #pragma unroll 4
        for (int d = 0; d < 128; d++) {
            float xv = sxT[d * 257 + t];
            unsigned long long xp = pk2(xv, xv);
            const unsigned long long* up =
                (const unsigned long long*)(suT + d * 10 + hh * 4);
            ffma2(a0, up[0], xp);
            ffma2(a1, up[1], xp);
        }
        float2 f0 = upk2(a0), f1 = upk2(a1);
        float cbase0 = sc[hh * 4 + 0], cbase1 = sc[hh * 4 + 1];
        float cbase2 = sc[hh * 4 + 2], cbase3 = sc[hh * 4 + 3];
        sbeta[t * 8 + hh * 4 + 0] = f0.x + cbase0;
        sbeta[t * 8 + hh * 4 + 1] = f0.y + cbase1;
        sbeta[t * 8 + hh * 4 + 2] = f1.x + cbase2;
        sbeta[t * 8 + hh * 4 + 3] = f1.y + cbase3;
    }
    __syncthreads();

    // ---- phase 3: softmax over t, warp per head ----
    if (tid < 256) {
        int h = tid >> 5, lane = tid & 31;
        float v[8];
        float m = -1e30f;
        #pragma unroll
        for (int i = 0; i < 8; i++) {
            v[i] = sbeta[(lane + 32 * i) * 8 + h];
            m = fmaxf(m, v[i]);
        }
        #pragma unroll
        for (int o = 16; o > 0; o >>= 1)
            m = fmaxf(m, __shfl_xor_sync(0xffffffffu, m, o));
        float ssum = 0.f;
        #pragma unroll
        for (int i = 0; i < 8; i++) { v[i] = __expf(v[i] - m); ssum += v[i]; }
        #pragma unroll
        for (int o = 16; o > 0; o >>= 1)
            ssum += __shfl_xor_sync(0xffffffffu, ssum, o);
        float inv = 1.f / ssum;
        #pragma unroll
        for (int i = 0; i < 8; i++)
            sbeta[(lane + 32 * i) * 8 + h] = v[i] * inv;
    }
    __syncthreads();

    // ---- phase 4: y[h,d] partials over t-quarters ----
    {
        const int d = tid & 127, g = tid >> 7;
        unsigned long long acc0 = 0, acc1 = 0, acc2 = 0, acc3 = 0;
        #pragma unroll 8
        for (int t = g * 64; t < g * 64 + 64; t++) {
            float xv = sxT[d * 257 + t];
            unsigned long long xp = pk2(xv, xv);
            const ulonglong2* bp = (const ulonglong2*)(sbeta + t * 8);
            ulonglong2 b01 = bp[0], b23 = bp[1];
            ffma2(acc0, b01.x, xp);
            ffma2(acc1, b01.y, xp);
            ffma2(acc2, b23.x, xp);
            ffma2(acc3, b23.y, xp);
        }
        float2 v0 = upk2(acc0), v1 = upk2(acc1), v2 = upk2(acc2), v3 = upk2(acc3);
        float* pg = spart + g * 1024;
        pg[0 * 128 + d] = v0.x;  pg[1 * 128 + d] = v0.y;
        pg[2 * 128 + d] = v1.x;  pg[3 * 128 + d] = v1.y;
        pg[4 * 128 + d] = v2.x;  pg[5 * 128 + d] = v2.y;
        pg[6 * 128 + d] = v3.x;  pg[7 * 128 + d] = v3.y;
    }
    __syncthreads();
    #pragma unroll
    for (int k = 0; k < 2; k++) {
        int i = tid + k * 512;
        sy[i] = spart[i] + spart[1024 + i] + spart[2048 + i] + spart[3072 + i];
    }
    __syncthreads();

    // ---- phase 5: out = sy @ M + cbias  (float4 M loads) ----
    {
        const int q = tid & 31, kg = tid >> 5;
        const float4* M4 = (const float4*)g_M;
        float4 acc = make_float4(0.f, 0.f, 0.f, 0.f);
        #pragma unroll 8
        for (int kk = 0; kk < 64; kk++) {
            int k = kg * 64 + kk;
            float yk = sy[k];
            float4 mv = M4[k * 32 + q];
            acc.x += yk * mv.x; acc.y += yk * mv.y;
            acc.z += yk * mv.z; acc.w += yk * mv.w;
        }
        ((float4*)spart)[kg * 32 + q] = acc;
    }
    __syncthreads();
    if (tid < 128) {
        float o = 0.f;
        #pragma unroll
        for (int p = 0; p < 8; p++) o += g_cbp[p * DD + tid];
        #pragma unroll
        for (int kg = 0; kg < 16; kg++) o += spart[kg * 128 + tid];
        out[b * DD + tid] = o;
    }
}

// ===========================================================================
extern "C" void kernel_launch(void* const* d_in, const int* in_sizes, int n_in,
                              void* d_out, int out_size) {
    const float* x  = (const float*)d_in[0];
    const float* Wq = (const float*)d_in[1];
    const float* bq = (const float*)d_in[2];
    const float* Wk = (const float*)d_in[3];
    const float* bk = (const float*)d_in[4];
    const float* Wv = (const float*)d_in[5];
    const float* bv = (const float*)d_in[6];
    const float* Ws = (const float*)d_in[7];
    const float* bs = (const float*)d_in[8];
    const float* Wo = (const float*)d_in[9];
    const float* bo = (const float*)d_in[10];
    float* out = (float*)d_out;

    static bool attr_done = false;
    if (!attr_done) {
        cudaFuncSetAttribute(k_main, cudaFuncAttributeMaxDynamicSharedMemorySize,
                             SMEM_K2_FLOATS * 4);
        attr_done = true;
    }

    k_pre<<<209, 256>>>(x, Ws, Wk, bk, Wq, bq, Wv, bv, Wo, bo);
    k_main<<<64, 512, SMEM_K2_FLOATS * 4>>>(x, bs, out);
}

// round 5
// speedup vs baseline: 2.9397x; 1.1152x over previous
#include <cuda_runtime.h>
#include <cstdint>

// Temporal_Attention — weight-space-collapsed; attention split across a
// 2-CTA cluster per batch (t-halves), DSMEM exchanges at phase boundaries.
// B=64, T=256, D=128, H=8, E=128.  out[B,D] fp32.

#define BB 64
#define TT 256
#define DD 128
#define HH 8
#define HE 1024
#define SCALE 0.088388347648318447f

static __device__ float g_S;
static __device__ __align__(16) float g_G[HH * DD * DD];
static __device__ __align__(16) float g_ub[HH * DD];
static __device__ __align__(16) float g_gb[HH * DD];
static __device__ float g_dqs[HH];
static __device__ __align__(16) float g_M[HE * DD];
static __device__ __align__(16) float g_cbp[8 * DD];

// ---- helpers ---------------------------------------------------------------
__device__ __forceinline__ void ffma2(unsigned long long& d,
                                      unsigned long long a, unsigned long long b) {
    asm("fma.rn.f32x2 %0, %1, %2, %0;" : "+l"(d) : "l"(a), "l"(b));
}
__device__ __forceinline__ unsigned long long pk2(float x, float y) {
    unsigned long long r;
    asm("mov.b64 %0, {%1, %2};" : "=l"(r) : "f"(x), "f"(y));
    return r;
}
__device__ __forceinline__ float2 upk2(unsigned long long v) {
    float lo, hi;
    asm("mov.b64 {%0, %1}, %2;" : "=f"(lo), "=f"(hi) : "l"(v));
    return make_float2(lo, hi);
}
__device__ __forceinline__ float dot4(float4 a, float4 b) {
    return a.x * b.x + a.y * b.y + a.z * b.z + a.w * b.w;
}
__device__ __forceinline__ uint32_t smem_u32(const void* p) {
    uint32_t a;
    asm("{ .reg .u64 t; cvta.to.shared.u64 t, %1; cvt.u32.u64 %0, t; }"
        : "=r"(a) : "l"(p));
    return a;
}
__device__ __forceinline__ uint32_t mapa_peer(uint32_t addr, uint32_t rank) {
    uint32_t r;
    asm("mapa.shared::cluster.u32 %0, %1, %2;" : "=r"(r) : "r"(addr), "r"(rank));
    return r;
}
__device__ __forceinline__ float ld_dsmem(uint32_t a) {
    float v;
    asm volatile("ld.shared::cluster.f32 %0, [%1];" : "=f"(v) : "r"(a));
    return v;
}
#define CLUSTER_SYNC() do { \
    asm volatile("barrier.cluster.arrive.aligned;" ::: "memory"); \
    asm volatile("barrier.cluster.wait.aligned;" ::: "memory"); \
} while (0)

// ===========================================================================
// K1: grid 145 x 256.  roles: G(0-63) | M(64-127) | gb(128-135)
//                             | cbias(136-143) | misc(144)
__global__ __launch_bounds__(256) void k_pre(
    const float* __restrict__ Ws,
    const float* __restrict__ Wk, const float* __restrict__ bk,
    const float* __restrict__ Wq, const float* __restrict__ bq,
    const float* __restrict__ Wv, const float* __restrict__ bv,
    const float* __restrict__ Wo, const float* __restrict__ bo)
{
    __shared__ __align__(16) float s[12288];   // 48 KB
    const int blk = blockIdx.x, tid = threadIdx.x;

    if (blk < 64) {
        // ------------- G role: G'[h, r0..r0+15, :] (+ub on rt==0) -------------
        const int w = blk, h = w >> 3, rt = w & 7, r0 = rt * 16;
        const int d2 = tid & 127, rg = tid >> 7;
        float4* wq4s = (float4*)s;            // [128][17] float4
        float4* wk4s = (float4*)(s + 8704);   // [16][16]
        float4* bk4s = (float4*)(s + 9728);   // [16]
        const float4* Wq4 = (const float4*)Wq;
        const float4* Wk4 = (const float4*)Wk;
        float acc[8];
        #pragma unroll
        for (int j = 0; j < 8; j++) acc[j] = 0.f;
        float ubacc = 0.f;
        for (int e0 = 0; e0 < 2; e0++) {           // e-chunks of 64
            #pragma unroll
            for (int k = 0; k < 8; k++) {
                int i = tid + k * 256;
                int dd = i >> 4, eq = i & 15;
                wq4s[dd * 17 + eq] = Wq4[dd * 256 + h * 32 + e0 * 16 + eq];
            }
            {
                int r = tid >> 4, eq = tid & 15;
                wk4s[r * 16 + eq] = Wk4[(r0 + r) * 256 + h * 32 + e0 * 16 + eq];
            }
            if (rt == 0 && tid < 16)
                bk4s[tid] = ((const float4*)bk)[h * 32 + e0 * 16 + tid];
            __syncthreads();
            #pragma unroll 4
            for (int e4 = 0; e4 < 16; e4++) {
                float4 q4 = wq4s[d2 * 17 + e4];
                #pragma unroll
                for (int j = 0; j < 8; j++)
                    acc[j] += dot4(q4, wk4s[(rg * 8 + j) * 16 + e4]);
                if (rt == 0 && rg == 0) ubacc += dot4(q4, bk4s[e4]);
            }
            __syncthreads();
        }
        #pragma unroll
        for (int j = 0; j < 8; j++)
            g_G[h * 16384 + (r0 + rg * 8 + j) * DD + d2] = SCALE * acc[j];
        if (rt == 0 && rg == 0) g_ub[h * DD + d2] = SCALE * ubacc;
    } else if (blk < 128) {
        // ------------- M role: M[h, r0..r0+15, :] -------------
        const int w = blk - 64, h = w >> 3, r0 = (w & 7) * 16;
        const int d2 = tid & 127, rh = tid >> 7;
        float* wo_s = s;            // 64 x 128
        float* wv_s = s + 8192;     // 16 x 64
        float acc[8];
        #pragma unroll
        for (int j = 0; j < 8; j++) acc[j] = 0.f;
        for (int e0 = 0; e0 < 128; e0 += 64) {
            for (int i = tid; i < 8192; i += 256) {
                int e = i >> 7, dd = i & 127;
                wo_s[i] = Wo[(h * 128 + e0 + e) * DD + dd];
            }
            for (int i = tid; i < 1024; i += 256) {
                int r = i >> 6, e = i & 63;
                wv_s[i] = Wv[(r0 + r) * HE + h * 128 + e0 + e];
            }
            __syncthreads();
            #pragma unroll 8
            for (int e = 0; e < 64; e++) {
                float wo = wo_s[e * 128 + d2];
                #pragma unroll
                for (int j = 0; j < 8; j++)
                    acc[j] += wv_s[(rh * 8 + j) * 64 + e] * wo;
            }
            __syncthreads();
        }
        #pragma unroll
        for (int j = 0; j < 8; j++)
            g_M[(h * 128 + r0 + rh * 8 + j) * DD + d2] = acc[j];
    } else if (blk < 136) {
        // ------------- gb role: gb'[h, :] -------------
        const int h = blk - 128, eq = tid & 31, dg = tid >> 5;
        float4 bqv = ((const float4*)bq)[h * 32 + eq];
        const float4* Wk4 = (const float4*)Wk;
        #pragma unroll
        for (int i = 0; i < 16; i++) {
            int dd = dg * 16 + i;
            float p = dot4(Wk4[dd * 256 + h * 32 + eq], bqv);
            #pragma unroll
            for (int o = 16; o > 0; o >>= 1)
                p += __shfl_xor_sync(0xffffffffu, p, o);
            if (eq == 0) g_gb[h * DD + dd] = SCALE * p;
        }
    } else if (blk < 144) {
        // ------------- cbias partial: k-slice p -------------
        const int p = blk - 136, d2 = tid & 127, kh = tid >> 7;
        float acc = 0.f;
        #pragma unroll 8
        for (int i = 0; i < 64; i++) {
            int k = p * 128 + kh * 64 + i;
            acc += __ldg(bv + k) * Wo[k * DD + d2];
        }
        s[tid] = acc;
        __syncthreads();
        if (kh == 0)
            g_cbp[p * DD + d2] = s[d2] + s[128 + d2] + (p == 0 ? bo[d2] : 0.f);
    } else {
        // ------------- misc: S, dq' -------------
        s[tid] = Ws[tid];
        {
            int h = tid >> 5, lane = tid & 31;
            float p = dot4(((const float4*)bk)[h * 32 + lane],
                           ((const float4*)bq)[h * 32 + lane]);
            #pragma unroll
            for (int o = 16; o > 0; o >>= 1)
                p += __shfl_xor_sync(0xffffffffu, p, o);
            if (lane == 0) g_dqs[h] = SCALE * p;
        }
        __syncthreads();
        for (int st = 128; st > 0; st >>= 1) {
            if (tid < st) s[tid] += s[tid + st];
            __syncthreads();
        }
        if (tid == 0) g_S = s[0];
    }
}

// ===========================================================================
// K2: cluster of 2 CTAs per batch; each CTA owns a t-half.
//   grid 128 x 512, dynamic smem.
//
// smem float offsets:
#define SXT_PAD   133
#define SXT_OFF   0        // [128 d][133]      17024
#define SWS_OFF   17024    // Ws half           128
#define XSP_OFF   17152    // xs partial        128
#define XSF_OFF   17280    // xs full           128
#define SUT_OFF   17408    // u  [d][8h]        1024
#define SBETA_OFF 18432    // beta [t][8h]      1024
#define SPART_OFF 19456    // scratch           4096
#define SYO_OFF   23552    // y own partial     1024
#define SYF_OFF   24576    // y full            1024
#define SMAX_OFF  25600    // 8
#define SSUM_OFF  25608    // 8
#define SF_OFF    25616    // 8
#define SC_OFF    25624    // 8
#define SMEM_K2_FLOATS 25664

__global__ __launch_bounds__(512) __cluster_dims__(2, 1, 1)
void k_main(const float* __restrict__ x, const float* __restrict__ Ws,
            const float* __restrict__ bs, float* __restrict__ out)
{
    extern __shared__ __align__(16) float sm[];
    float* sxT    = sm + SXT_OFF;
    float* sWs    = sm + SWS_OFF;
    float* xs_prt = sm + XSP_OFF;
    float* xs_fl  = sm + XSF_OFF;
    float* suT    = sm + SUT_OFF;
    float* sbeta  = sm + SBETA_OFF;
    float* spart  = sm + SPART_OFF;
    float* sy_own = sm + SYO_OFF;
    float* sy_fl  = sm + SYF_OFF;
    float* smax_s = sm + SMAX_OFF;
    float* ssum_s = sm + SSUM_OFF;
    float* sf     = sm + SF_OFF;
    float* sc     = sm + SC_OFF;

    const int tid = threadIdx.x;
    uint32_t rank;
    asm("mov.u32 %0, %%cluster_ctarank;" : "=r"(rank));
    const int r = (int)rank;
    const uint32_t peer = 1u - rank;
    const int b = blockIdx.x >> 1;

    // ---- phase 0: fill own x tile (transposed) + xs partial over own t-half
    if (tid < 128) sWs[tid] = Ws[r * 128 + tid];
    __syncthreads();
    {
        const int d = tid & 127, tg = tid >> 7;
        const float* xb = x + ((size_t)b * TT + r * 128) * DD + d;
        float acc = 0.f;
        #pragma unroll
        for (int k = 0; k < 32; k++) {
            int t = k * 4 + tg;
            float v = xb[t * DD];
            sxT[d * SXT_PAD + t] = v;
            acc += sWs[t] * v;
        }
        spart[tg * 128 + d] = acc;
    }
    __syncthreads();
    if (tid < 128)
        xs_prt[tid] = spart[tid] + spart[128 + tid] + spart[256 + tid] + spart[384 + tid];
    CLUSTER_SYNC();   // #1: xs partials visible cluster-wide

    // ---- phase 1: xs full, c[h], u (own d-half)
    if (tid < 128) {
        uint32_t la = smem_u32(xs_prt + tid);
        xs_fl[tid] = xs_prt[tid] + ld_dsmem(mapa_peer(la, peer));
    }
    __syncthreads();
    if (tid < 256) {
        int h = tid >> 5, lane = tid & 31;
        float p = dot4(((const float4*)xs_fl)[lane],
                       ((const float4*)g_gb)[h * 32 + lane]);
        #pragma unroll
        for (int o = 16; o > 0; o >>= 1)
            p += __shfl_xor_sync(0xffffffffu, p, o);
        if (lane == 0) sc[h] = p + g_S * g_dqs[h] + bs[0];
    }
    {
        const int h = tid >> 6, dq = tid & 63;
        const int d = r * 64 + dq;
        const float* Gp = g_G + h * 16384 + d;
        float a0 = g_S * g_ub[h * 128 + d], a1 = 0.f;
        #pragma unroll 8
        for (int dp = 0; dp < 128; dp += 2) {
            a0 += xs_fl[dp]     * Gp[dp * 128];
            a1 += xs_fl[dp + 1] * Gp[dp * 128 + 128];
        }
        suT[d * 8 + h] = a0 + a1;
    }
    CLUSTER_SYNC();   // #2: u own-halves visible

    // ---- phase 2: fetch peer u half; summary over own t-half
    {
        const int dpq = tid >> 3, h = tid & 7;
        const int d = (int)peer * 64 + dpq;
        uint32_t la = smem_u32(suT + d * 8 + h);
        float v = ld_dsmem(mapa_peer(la, peer));
        suT[d * 8 + h] = v;   // disjoint from indices peer reads (our r-half)
    }
    __syncthreads();
    {
        const int t = tid & 127, g = tid >> 7;
        unsigned long long a0 = 0, a1 = 0, a2 = 0, a3 = 0;
        #pragma unroll 8
        for (int d = g * 32; d < g * 32 + 32; d++) {
            float xv = sxT[d * SXT_PAD + t];
            unsigned long long xp = pk2(xv, xv);
            const unsigned long long* up = (const unsigned long long*)(suT + d * 8);
            ffma2(a0, up[0], xp); ffma2(a1, up[1], xp);
            ffma2(a2, up[2], xp); ffma2(a3, up[3], xp);
        }
        unsigned long long* sp = (unsigned long long*)spart;
        sp[(g * 128 + t) * 4 + 0] = a0; sp[(g * 128 + t) * 4 + 1] = a1;
        sp[(g * 128 + t) * 4 + 2] = a2; sp[(g * 128 + t) * 4 + 3] = a3;
    }
    __syncthreads();
    #pragma unroll
    for (int k = 0; k < 2; k++) {
        int i = tid + k * 512;           // i = t*8 + h
        int h = i & 7;
        sbeta[i] = spart[i] + spart[1024 + i] + spart[2048 + i] + spart[3072 + i] + sc[h];
    }
    __syncthreads();

    // ---- phase 3: own-half softmax stats; store e^{v-m_own}
    if (tid < 256) {
        int h = tid >> 5, lane = tid & 31;
        float v[4];
        float m = -1e30f;
        #pragma unroll
        for (int i = 0; i < 4; i++) {
            v[i] = sbeta[(lane + 32 * i) * 8 + h];
            m = fmaxf(m, v[i]);
        }
        #pragma unroll
        for (int o = 16; o > 0; o >>= 1)
            m = fmaxf(m, __shfl_xor_sync(0xffffffffu, m, o));
        float ssum = 0.f;
        #pragma unroll
        for (int i = 0; i < 4; i++) { v[i] = __expf(v[i] - m); ssum += v[i]; }
        #pragma unroll
        for (int o = 16; o > 0; o >>= 1)
            ssum += __shfl_xor_sync(0xffffffffu, ssum, o);
        #pragma unroll
        for (int i = 0; i < 4; i++) sbeta[(lane + 32 * i) * 8 + h] = v[i];
        if (lane == 0) { smax_s[h] = m; ssum_s[h] = ssum; }
    }
    CLUSTER_SYNC();   // #3: stats visible
    if (tid < 8) {
        float mo = smax_s[tid], so = ssum_s[tid];
        float mp = ld_dsmem(mapa_peer(smem_u32(smax_s + tid), peer));
        float spd = ld_dsmem(mapa_peer(smem_u32(ssum_s + tid), peer));
        float m = fmaxf(mo, mp);
        float denom = so * __expf(mo - m) + spd * __expf(mp - m);
        sf[tid] = __expf(mo - m) / denom;
    }
    __syncthreads();

    // ---- phase 4: y partial over own t-half (renorm folded via sf)
    {
        const int d = tid & 127, g = tid >> 7;
        unsigned long long a0 = 0, a1 = 0, a2 = 0, a3 = 0;
        #pragma unroll 8
        for (int t = g * 32; t < g * 32 + 32; t++) {
            float xv = sxT[d * SXT_PAD + t];
            unsigned long long xp = pk2(xv, xv);
            const ulonglong2* bp = (const ulonglong2*)(sbeta + t * 8);
            ulonglong2 b01 = bp[0], b23 = bp[1];
            ffma2(a0, b01.x, xp); ffma2(a1, b01.y, xp);
            ffma2(a2, b23.x, xp); ffma2(a3, b23.y, xp);
        }
        float2 v0 = upk2(a0), v1 = upk2(a1), v2 = upk2(a2), v3 = upk2(a3);
        float* pg = spart + g * 1024;
        pg[0 * 128 + d] = v0.x; pg[1 * 128 + d] = v0.y;
        pg[2 * 128 + d] = v1.x; pg[3 * 128 + d] = v1.y;
        pg[4 * 128 + d] = v2.x; pg[5 * 128 + d] = v2.y;
        pg[6 * 128 + d] = v3.x; pg[7 * 128 + d] = v3.y;
    }
    __syncthreads();
    #pragma unroll
    for (int k = 0; k < 2; k++) {
        int i = tid + k * 512;
        int h = i >> 7;
        sy_own[i] = sf[h] * (spart[i] + spart[1024 + i] + spart[2048 + i] + spart[3072 + i]);
    }
    CLUSTER_SYNC();   // #4: y partials visible
    #pragma unroll
    for (int k = 0; k < 2; k++) {
        int i = tid + k * 512;
        uint32_t la = smem_u32(sy_own + i);
        sy_fl[i] = sy_own[i] + ld_dsmem(mapa_peer(la, peer));
    }
    __syncthreads();

    // ---- phase 5: out own d2-half = sy_full . M[:, half] + cbias
    {
        const int q = tid & 15, kg = tid >> 4;
        const float4* M4 = ((const float4*)g_M) + r * 16 + q;
        float4 acc = make_float4(0.f, 0.f, 0.f, 0.f);
        #pragma unroll 8
        for (int kk = 0; kk < 32; kk++) {
            int k = kg * 32 + kk;
            float yk = sy_fl[k];
            float4 mv = M4[k * 32];
            acc.x += yk * mv.x; acc.y += yk * mv.y;
            acc.z += yk * mv.z; acc.w += yk * mv.w;
        }
        ((float4*)spart)[kg * 16 + q] = acc;
    }
    __syncthreads();
    if (tid < 64) {
        float o = 0.f;
        #pragma unroll
        for (int p = 0; p < 8; p++) o += g_cbp[p * DD + r * 64 + tid];
        #pragma unroll
        for (int kg = 0; kg < 32; kg++) o += spart[kg * 64 + tid];
        out[b * DD + r * 64 + tid] = o;
    }
    CLUSTER_SYNC();   // final: no CTA exits while peer may read its smem
}

// ===========================================================================
extern "C" void kernel_launch(void* const* d_in, const int* in_sizes, int n_in,
                              void* d_out, int out_size) {
    const float* x  = (const float*)d_in[0];
    const float* Wq = (const float*)d_in[1];
    const float* bq = (const float*)d_in[2];
    const float* Wk = (const float*)d_in[3];
    const float* bk = (const float*)d_in[4];
    const float* Wv = (const float*)d_in[5];
    const float* bv = (const float*)d_in[6];
    const float* Ws = (const float*)d_in[7];
    const float* bs = (const float*)d_in[8];
    const float* Wo = (const float*)d_in[9];
    const float* bo = (const float*)d_in[10];
    float* out = (float*)d_out;

    static bool attr_done = false;
    if (!attr_done) {
        cudaFuncSetAttribute(k_main, cudaFuncAttributeMaxDynamicSharedMemorySize,
                             SMEM_K2_FLOATS * 4);
        attr_done = true;
    }

    k_pre<<<145, 256>>>(Ws, Wk, bk, Wq, bq, Wv, bv, Wo, bo);
    k_main<<<128, 512, SMEM_K2_FLOATS * 4>>>(x, Ws, bs, out);
}